// round 14
// baseline (speedup 1.0000x reference)
#include <cuda_runtime.h>
#include <cuda_bf16.h>
#include <cstdint>
#include <math.h>

// Problem constants
#define BB 64
#define NN 16384
#define QQ 2048          // Q_LIDAR
#define NC 23            // NUM_CLASSES
#define DD 512           // MODEL_DIM
#define INF 33           // INPUT_DIM
#define K1P 48           // padded stage-1 K (33 -> 48, 3 x k16)
#define MM (BB * QQ)     // 131072 total selected rows
#define FEAT_LD 36       // padded feature stride

// Output layout: queries [B,Q,512] | refs [B,Q,3] | scores [B,Q]  (all f32)
#define OUT_Q_OFF 0
#define OUT_R_OFF ((size_t)BB * QQ * DD)
#define OUT_S_OFF (OUT_R_OFF + (size_t)BB * QQ * 3)

// ---- device scratch (no allocations allowed) ----
__device__ __align__(16) unsigned long long g_keys[(size_t)BB * NN];   // 8 MB
__device__ int g_idx[BB * QQ];                                         // 512 KB
__device__ __align__(16) float g_feat[(size_t)MM * FEAT_LD];           // ~19 MB
__device__ unsigned char g_validsel[MM];                               // 128 KB
__device__ __align__(16) __nv_bfloat16 g_hid_hi[(size_t)MM * DD];      // 134 MB
__device__ __align__(16) __nv_bfloat16 g_hid_lo[(size_t)MM * DD];      // 134 MB
__device__ __align__(16) __nv_bfloat16 g_w1t_hi[(size_t)DD * K1P];     // 48 KB [n][k]
__device__ __align__(16) __nv_bfloat16 g_w1t_lo[(size_t)DD * K1P];
__device__ __align__(16) __nv_bfloat16 g_w2t_hi[(size_t)DD * DD];      // 512 KB [n][k]
__device__ __align__(16) __nv_bfloat16 g_w2t_lo[(size_t)DD * DD];

// Canonicalized inputs (robust to input order / dtype conversion)
__device__ unsigned long long g_ptr_scores, g_ptr_labels, g_ptr_valid;
__device__ int g_lab_mode;   // 0=int32, 1=int64, 2=float32
__device__ int g_val_mode;   // 0=uint8, 1=int32, 2=float32
__device__ __align__(16) float g_scores_c[(size_t)BB * NN];
__device__ __align__(16) int   g_labels_c[(size_t)BB * NN];
__device__ unsigned char g_valid_c[(size_t)BB * NN];

// ============================================================================
// Kernel 0a: classify the three 1048576-element buffers by content.
// ============================================================================
__global__ void k_classify(const unsigned* c0, const unsigned* c1, const unsigned* c2) {
    const unsigned* cands[3] = {c0, c1, c2};
    __shared__ int cls[3], mode[3];
    for (int ci = 0; ci < 3; ++ci) {
        const unsigned* p = cands[ci];
        int bytes01 = 1, words01 = 1, lt23 = 1, oddz = 1, fbool = 1, fint = 1;
        for (int i = threadIdx.x; i < 1024; i += blockDim.x) {
            unsigned w = p[i];
            unsigned b0 = w & 255u, b1 = (w >> 8) & 255u, b2 = (w >> 16) & 255u, b3 = w >> 24;
            if (b0 > 1u || b1 > 1u || b2 > 1u || b3 > 1u) bytes01 = 0;
            if (w > 1u) words01 = 0;
            if (w >= 23u) lt23 = 0;
            if ((i & 1) && w) oddz = 0;
            float f = __uint_as_float(w);
            if (!(f == 0.0f || f == 1.0f)) fbool = 0;
            if (!(f == 0.0f || (f >= 1.0f && f < 23.0f && f == floorf(f)))) fint = 0;
        }
        bytes01 = __syncthreads_and(bytes01);
        words01 = __syncthreads_and(words01);
        lt23    = __syncthreads_and(lt23);
        oddz    = __syncthreads_and(oddz);
        fbool   = __syncthreads_and(fbool);
        fint    = __syncthreads_and(fint);
        if (threadIdx.x == 0) {
            if (bytes01)      { cls[ci] = 2; mode[ci] = words01 ? 1 : 0; }
            else if (lt23)    { cls[ci] = 1; mode[ci] = oddz ? 1 : 0; }
            else if (fbool)   { cls[ci] = 2; mode[ci] = 2; }
            else if (fint)    { cls[ci] = 1; mode[ci] = 2; }
            else              { cls[ci] = 0; mode[ci] = 0; }
        }
        __syncthreads();
    }
    if (threadIdx.x == 0) {
        bool ok = (cls[0] + cls[1] + cls[2] == 3) &&
                  cls[0] != cls[1] && cls[0] != cls[2] && cls[1] != cls[2];
        if (!ok) { cls[0] = 0; cls[1] = 1; cls[2] = 2; mode[1] = 1; mode[2] = 0; }
        for (int ci = 0; ci < 3; ++ci) {
            unsigned long long pv = (unsigned long long)cands[ci];
            if (cls[ci] == 0)      g_ptr_scores = pv;
            else if (cls[ci] == 1) { g_ptr_labels = pv; g_lab_mode = mode[ci]; }
            else                   { g_ptr_valid = pv;  g_val_mode = mode[ci]; }
        }
    }
}

// ============================================================================
// Kernel 0b: canonicalize + build sort keys (fused).
// ============================================================================
__global__ void k_canon_keys() {
    int t = blockIdx.x * blockDim.x + threadIdx.x;
    if (t >= BB * NN) return;
    const unsigned* sp = (const unsigned*)g_ptr_scores;
    float sc = __uint_as_float(sp[t]);
    g_scores_c[t] = sc;

    const unsigned* lp = (const unsigned*)g_ptr_labels;
    int lm = g_lab_mode;
    int lab = (lm == 1) ? (int)lp[2 * t]
            : (lm == 2) ? (int)__uint_as_float(lp[t])
                        : (int)lp[t];
    g_labels_c[t] = lab;

    int vm = g_val_mode;
    unsigned char v;
    if (vm == 0)      v = (((const unsigned char*)g_ptr_valid)[t] != 0);
    else if (vm == 1) v = (((const unsigned*)g_ptr_valid)[t] != 0u);
    else              v = (__uint_as_float(((const unsigned*)g_ptr_valid)[t]) != 0.0f);
    g_valid_c[t] = v;

    float s = v ? sc : -1e30f;
    unsigned u = __float_as_uint(s);
    u = (u & 0x80000000u) ? ~u : (u | 0x80000000u);
    unsigned i = (unsigned)(t & (NN - 1));
    g_keys[t] = ((unsigned long long)u << 32) | (unsigned)(~i);
}

// ============================================================================
// Kernel 2: per-batch exact top-K (ordered). One CTA per batch. 1024 threads.
// Vectorized ulonglong2 scans (keys are 16B aligned, NN even).
// ============================================================================
__global__ void k_select_topk() {
    __shared__ unsigned long long skey[QQ];
    __shared__ unsigned int hist[256];
    __shared__ int s_digit, s_k;
    __shared__ unsigned int s_cnt;

    const int b = blockIdx.x;
    const int tid = threadIdx.x;
    const int bd = blockDim.x;
    const unsigned long long* keys = g_keys + (size_t)b * NN;
    const ulonglong2* keys2 = (const ulonglong2*)keys;

    unsigned long long prefix = 0;
    int k = QQ;

    #pragma unroll 1
    for (int pass = 0; pass < 8; ++pass) {
        const int shift = 56 - pass * 8;
        const unsigned long long mask = pass ? (~0ULL << (64 - 8 * pass)) : 0ULL;
        for (int i = tid; i < 256; i += bd) hist[i] = 0;
        __syncthreads();
        for (int i = tid; i < NN / 2; i += bd) {
            ulonglong2 kv = keys2[i];
            if ((kv.x & mask) == prefix)
                atomicAdd(&hist[(unsigned)(kv.x >> shift) & 0xFFu], 1u);
            if ((kv.y & mask) == prefix)
                atomicAdd(&hist[(unsigned)(kv.y >> shift) & 0xFFu], 1u);
        }
        __syncthreads();
        if (tid == 0) {
            int run = 0, d = 255;
            for (; d >= 0; --d) {
                int h = (int)hist[d];
                if (run + h >= k) break;
                run += h;
            }
            s_digit = d;
            s_k = k - run;
        }
        __syncthreads();
        prefix |= ((unsigned long long)(unsigned)s_digit) << shift;
        k = s_k;
        __syncthreads();
    }
    const unsigned long long thr = prefix;

    if (tid == 0) s_cnt = 0;
    for (int i = tid; i < QQ; i += bd) skey[i] = 0;
    __syncthreads();
    for (int i = tid; i < NN / 2; i += bd) {
        ulonglong2 kv = keys2[i];
        if (kv.x >= thr) {
            unsigned p = atomicAdd(&s_cnt, 1u);
            if (p < QQ) skey[p] = kv.x;
        }
        if (kv.y >= thr) {
            unsigned p = atomicAdd(&s_cnt, 1u);
            if (p < QQ) skey[p] = kv.y;
        }
    }
    __syncthreads();

    for (int kk = 2; kk <= QQ; kk <<= 1) {
        for (int j = kk >> 1; j > 0; j >>= 1) {
            for (int t = tid; t < QQ; t += bd) {
                int ixj = t ^ j;
                if (ixj > t) {
                    unsigned long long a = skey[t], c = skey[ixj];
                    bool desc = ((t & kk) == 0);
                    if (desc ? (a < c) : (a > c)) { skey[t] = c; skey[ixj] = a; }
                }
            }
            __syncthreads();
        }
    }

    for (int t = tid; t < QQ; t += bd)
        g_idx[b * QQ + t] = (int)(~(unsigned)(skey[t] & 0xFFFFFFFFULL));
}

// ============================================================================
// Kernel 3: gather features + write refs/scores outputs (float4 feat stores).
// ============================================================================
__global__ void k_gather(const float* __restrict__ boxes,
                         float* __restrict__ out) {
    int r = blockIdx.x * blockDim.x + threadIdx.x;
    if (r >= MM) return;
    int b = r >> 11;
    int i = g_idx[r];
    size_t src = (size_t)b * NN + i;

    const float* bx = boxes + src * 9;
    float sc = g_scores_c[src];
    int lab = g_labels_c[src];
    unsigned char v = g_valid_c[src];

    __align__(16) float buf[36];
    #pragma unroll
    for (int j = 0; j < 9; ++j) buf[j] = bx[j];
    buf[9] = sc;
    #pragma unroll
    for (int c = 0; c < NC; ++c) buf[10 + c] = (c == lab) ? 1.0f : 0.0f;
    buf[33] = 0.0f; buf[34] = 0.0f; buf[35] = 0.0f;

    float4* fr4 = (float4*)(g_feat + (size_t)r * FEAT_LD);
    const float4* b4 = (const float4*)buf;
    #pragma unroll
    for (int j = 0; j < 9; ++j) fr4[j] = b4[j];

    g_validsel[r] = v;

    float* refo = out + OUT_R_OFF + (size_t)r * 3;
    refo[0] = v ? buf[0] : 0.0f;
    refo[1] = v ? buf[1] : 0.0f;
    refo[2] = v ? buf[2] : 0.0f;
    out[OUT_S_OFF + r] = v ? sc : 0.0f;
}

// ============================================================================
// Kernel 3b: weight prep. w1 -> w1t[n][48] split; w2 -> w2t[n][k] split.
// ============================================================================
__global__ void k_prep_w1(const float* __restrict__ w1) {
    int idx = blockIdx.x * blockDim.x + threadIdx.x;
    if (idx >= DD * K1P) return;
    int n = idx / K1P, k = idx - n * K1P;
    float v = (k < INF) ? w1[(size_t)k * DD + n] : 0.0f;
    __nv_bfloat16 hi = __float2bfloat16(v);
    g_w1t_hi[idx] = hi;
    g_w1t_lo[idx] = __float2bfloat16(v - __bfloat162float(hi));
}
__global__ void k_prep_w2(const float* __restrict__ w2) {
    int idx = blockIdx.x * blockDim.x + threadIdx.x;
    if (idx >= DD * DD) return;
    int n = idx >> 9, k = idx & (DD - 1);
    float v = w2[(size_t)k * DD + n];
    __nv_bfloat16 hi = __float2bfloat16(v);
    g_w2t_hi[idx] = hi;
    g_w2t_lo[idx] = __float2bfloat16(v - __bfloat162float(hi));
}

// ============================================================================
// mma helpers
// ============================================================================
__device__ __forceinline__ uint32_t smem_u32(const void* p) {
    uint32_t a;
    asm("{ .reg .u64 t; cvta.to.shared.u64 t, %1; cvt.u32.u64 %0, t; }" : "=r"(a) : "l"(p));
    return a;
}
__device__ __forceinline__ void ldm_x4(uint32_t* r, uint32_t addr) {
    asm volatile("ldmatrix.sync.aligned.m8n8.x4.shared.b16 {%0,%1,%2,%3}, [%4];"
        : "=r"(r[0]), "=r"(r[1]), "=r"(r[2]), "=r"(r[3]) : "r"(addr));
}
__device__ __forceinline__ void mma_bf16(float* c, const uint32_t* a, uint32_t b0, uint32_t b1) {
    asm volatile("mma.sync.aligned.m16n8k16.row.col.f32.bf16.bf16.f32 "
        "{%0,%1,%2,%3}, {%4,%5,%6,%7}, {%8,%9}, {%0,%1,%2,%3};"
        : "+f"(c[0]), "+f"(c[1]), "+f"(c[2]), "+f"(c[3])
        : "r"(a[0]), "r"(a[1]), "r"(a[2]), "r"(a[3]), "r"(b0), "r"(b1));
}
__device__ __forceinline__ void cp16(uint32_t dst, const void* src) {
    asm volatile("cp.async.cg.shared.global [%0], [%1], 16;" :: "r"(dst), "l"(src));
}
__device__ __forceinline__ void split_pack(float a, float b, uint32_t& hip, uint32_t& lop) {
    __nv_bfloat16 ha = __float2bfloat16(a), hb = __float2bfloat16(b);
    __nv_bfloat16 la = __float2bfloat16(a - __bfloat162float(ha));
    __nv_bfloat16 lb = __float2bfloat16(b - __bfloat162float(hb));
    hip = (uint32_t)__bfloat16_as_ushort(ha) | ((uint32_t)__bfloat16_as_ushort(hb) << 16);
    lop = (uint32_t)__bfloat16_as_ushort(la) | ((uint32_t)__bfloat16_as_ushort(lb) << 16);
}

// ============================================================================
// Kernel 4: GEMM1 tensorized (R9-identical). hidden = relu(feat @ w1 + b1).
// CTA 128x256, 8 warps (2m x 4n), warp tile 64x64. grid (2, M/128).
// ============================================================================
#define G1_FP 56
#define G1_WP 56
#define G1_OFF_FH 0
#define G1_OFF_FL 14336
#define G1_OFF_WH 28672
#define G1_OFF_WL 57344
#define G1_SMEM   86016

__global__ void __launch_bounds__(256, 1) k_gemm1t(const float* __restrict__ b1) {
    extern __shared__ __align__(16) char smem[];
    const uint32_t sb = smem_u32(smem);
    const int tid = threadIdx.x;
    const int wid = tid >> 5, lane = tid & 31;
    const int mwarp = wid & 1;
    const int nwarp = wid >> 1;
    const int row0 = blockIdx.y * 128;
    const int col0 = blockIdx.x * 256;

    const int qr = lane >> 2, qc = (lane & 3) * 2;
    const int a_r = lane & 15;
    const int a_k = (lane >> 4) * 8;
    const int b_r = (lane & 7) + (lane >> 4) * 8;
    const int b_k = ((lane >> 3) & 1) * 8;

    #pragma unroll
    for (int it = 0; it < 6; ++it) {
        int idx = tid + it * 256;
        int n = idx / 6, p = idx - n * 6;
        uint32_t d = sb + G1_OFF_WH + n * (G1_WP * 2) + p * 16;
        size_t so = ((size_t)(col0 + n) * K1P + p * 8);
        cp16(d, g_w1t_hi + so);
        cp16(d + (G1_OFF_WL - G1_OFF_WH), g_w1t_lo + so);
    }
    asm volatile("cp.async.commit_group;" ::: "memory");

    #pragma unroll
    for (int it = 0; it < 28; ++it) {
        int idx = tid + it * 256;
        *(uint32_t*)(smem + idx * 4) = 0u;
    }
    __syncthreads();
    for (int idx = tid; idx < 128 * INF; idx += 256) {
        int r = idx / INF, c = idx - r * INF;
        float v = g_feat[(size_t)(row0 + r) * FEAT_LD + c];
        __nv_bfloat16 hi = __float2bfloat16(v);
        __nv_bfloat16 lo = __float2bfloat16(v - __bfloat162float(hi));
        *(__nv_bfloat16*)(smem + G1_OFF_FH + (r * G1_FP + c) * 2) = hi;
        *(__nv_bfloat16*)(smem + G1_OFF_FL + (r * G1_FP + c) * 2) = lo;
    }
    asm volatile("cp.async.wait_group 0;" ::: "memory");
    __syncthreads();

    float acc[4][8][4];
    #pragma unroll
    for (int mi = 0; mi < 4; ++mi)
        #pragma unroll
        for (int ni = 0; ni < 8; ++ni)
            #pragma unroll
            for (int q = 0; q < 4; ++q) acc[mi][ni][q] = 0.0f;

    const uint32_t uFh = sb + G1_OFF_FH, uFl = sb + G1_OFF_FL;
    const uint32_t uWh = sb + G1_OFF_WH, uWl = sb + G1_OFF_WL;
    #pragma unroll
    for (int kk = 0; kk < 3; ++kk) {
        const int kh = kk * 16;
        uint32_t fAh[4][4], fAl[4][4];
        #pragma unroll
        for (int mi = 0; mi < 4; ++mi) {
            uint32_t ao = (uint32_t)(((mwarp * 64 + mi * 16 + a_r) * G1_FP + kh + a_k) * 2);
            ldm_x4(fAh[mi], uFh + ao);
            ldm_x4(fAl[mi], uFl + ao);
        }
        #pragma unroll
        for (int nb = 0; nb < 4; ++nb) {
            uint32_t bh[4], bl[4];
            uint32_t bo = (uint32_t)(((nwarp * 64 + nb * 16 + b_r) * G1_WP + kh + b_k) * 2);
            ldm_x4(bh, uWh + bo);
            ldm_x4(bl, uWl + bo);
            #pragma unroll
            for (int mi = 0; mi < 4; ++mi) {
                mma_bf16(acc[mi][nb * 2 + 0], fAh[mi], bh[0], bh[1]);
                mma_bf16(acc[mi][nb * 2 + 1], fAh[mi], bh[2], bh[3]);
                mma_bf16(acc[mi][nb * 2 + 0], fAh[mi], bl[0], bl[1]);
                mma_bf16(acc[mi][nb * 2 + 1], fAh[mi], bl[2], bl[3]);
                mma_bf16(acc[mi][nb * 2 + 0], fAl[mi], bh[0], bh[1]);
                mma_bf16(acc[mi][nb * 2 + 1], fAl[mi], bh[2], bh[3]);
            }
        }
    }

    #pragma unroll
    for (int mi = 0; mi < 4; ++mi) {
        int r1 = row0 + mwarp * 64 + mi * 16 + qr;
        int r2 = r1 + 8;
        #pragma unroll
        for (int ni = 0; ni < 8; ++ni) {
            int cg = col0 + nwarp * 64 + ni * 8 + qc;
            float ba = b1[cg], bb = b1[cg + 1];
            float h1a = fmaxf(acc[mi][ni][0] + ba, 0.0f);
            float h1b = fmaxf(acc[mi][ni][1] + bb, 0.0f);
            float h2a = fmaxf(acc[mi][ni][2] + ba, 0.0f);
            float h2b = fmaxf(acc[mi][ni][3] + bb, 0.0f);
            uint32_t hp, lp;
            split_pack(h1a, h1b, hp, lp);
            *(uint32_t*)&g_hid_hi[(size_t)r1 * DD + cg] = hp;
            *(uint32_t*)&g_hid_lo[(size_t)r1 * DD + cg] = lp;
            split_pack(h2a, h2b, hp, lp);
            *(uint32_t*)&g_hid_hi[(size_t)r2 * DD + cg] = hp;
            *(uint32_t*)&g_hid_lo[(size_t)r2 * DD + cg] = lp;
        }
    }
}

// ============================================================================
// Kernel 5: GEMM2. mma.sync bf16, 3-term split, cp.async 2-stage pipeline.
// CTA tile 128x256, 512 threads = 16 warps (2m x 8n), warp tile 64x32,
// BK=64 (8 chunks), pitch 72 halves. 4 warps/SMSP for latency hiding;
// acc 64 regs/thread fits the 128-reg cap at occ 1.
// ============================================================================
#define ALD2 72
#define A_SZ 18432        // 128*72*2
#define B_SZ 36864        // 256*72*2
#define OFF_AH 0
#define OFF_AL A_SZ
#define OFF_BH (2 * A_SZ)
#define OFF_BL (2 * A_SZ + B_SZ)
#define STAGE_SZ (2 * A_SZ + 2 * B_SZ)   // 110592
#define G2_SMEM (2 * STAGE_SZ)           // 221184

__global__ void __launch_bounds__(512, 1) k_gemm2_mma(const float* __restrict__ b2,
                                                      float* __restrict__ out) {
    extern __shared__ __align__(16) char smem[];
    const uint32_t sb = smem_u32(smem);

    const int tid = threadIdx.x;
    const int wid = tid >> 5, lane = tid & 31;
    const int mwarp = wid & 1;        // 2 m-groups of 64 rows
    const int nwarp = wid >> 1;       // 8 n-groups of 32 cols
    const int row0 = blockIdx.y * 128;
    const int col0 = blockIdx.x * 256;

    const __nv_bfloat16* Ah = g_hid_hi + (size_t)row0 * DD;
    const __nv_bfloat16* Al = g_hid_lo + (size_t)row0 * DD;
    const __nv_bfloat16* Bh = g_w2t_hi + (size_t)col0 * DD;
    const __nv_bfloat16* Bl = g_w2t_lo + (size_t)col0 * DD;

    const int a_row = mwarp * 64 + (lane & 15);                    // + mi*16
    const int a_kof = (lane >> 4) * 8;
    const int b_row = nwarp * 32 + (lane & 7) + (lane >> 4) * 8;   // + nb*16
    const int b_kof = ((lane >> 3) & 1) * 8;

    float acc[4][4][4];   // [mi][ni(n8)][quad]
    #pragma unroll
    for (int mi = 0; mi < 4; ++mi)
        #pragma unroll
        for (int ni = 0; ni < 4; ++ni)
            #pragma unroll
            for (int q = 0; q < 4; ++q) acc[mi][ni][q] = 0.0f;

    auto load_chunk = [&](int c, int stage) {
        const int kc = c * 64;
        const uint32_t sbase = sb + stage * STAGE_SZ;
        #pragma unroll
        for (int it = 0; it < 2; ++it) {             // A: 128 rows x 64 halves
            int idx = tid + it * 512;                // 1024 pieces of 16 B
            int r = idx >> 3, p = idx & 7;
            size_t src = (size_t)r * DD + kc + p * 8;
            uint32_t d = sbase + OFF_AH + r * (ALD2 * 2) + p * 16;
            cp16(d, Ah + src);
            cp16(d + A_SZ, Al + src);
        }
        #pragma unroll
        for (int it = 0; it < 4; ++it) {             // B: 256 rows x 64 halves
            int idx = tid + it * 512;                // 2048 pieces
            int n = idx >> 3, p = idx & 7;
            size_t src = (size_t)n * DD + kc + p * 8;
            uint32_t d = sbase + OFF_BH + n * (ALD2 * 2) + p * 16;
            cp16(d, Bh + src);
            cp16(d + B_SZ, Bl + src);
        }
        asm volatile("cp.async.commit_group;" ::: "memory");
    };

    load_chunk(0, 0);

    #pragma unroll 1
    for (int c = 0; c < 8; ++c) {
        if (c + 1 < 8) {
            load_chunk(c + 1, (c + 1) & 1);
            asm volatile("cp.async.wait_group 1;" ::: "memory");
        } else {
            asm volatile("cp.async.wait_group 0;" ::: "memory");
        }
        __syncthreads();

        const uint32_t sbase = sb + (c & 1) * STAGE_SZ;
        const uint32_t uAh = sbase + OFF_AH, uAl = sbase + OFF_AL;
        const uint32_t uBh = sbase + OFF_BH, uBl = sbase + OFF_BL;

        #pragma unroll
        for (int kk = 0; kk < 4; ++kk) {
            const int kh = kk * 16;
            // hoist both n16 B fragments for this kk
            uint32_t bh[2][4], bl[2][4];
            #pragma unroll
            for (int nb = 0; nb < 2; ++nb) {
                uint32_t bo = (uint32_t)(((b_row + nb * 16) * ALD2 + kh + b_kof) * 2);
                ldm_x4(bh[nb], uBh + bo);
                ldm_x4(bl[nb], uBl + bo);
            }
            #pragma unroll
            for (int mi = 0; mi < 4; ++mi) {
                uint32_t fAh[4], fAl[4];
                uint32_t ao = (uint32_t)(((a_row + mi * 16) * ALD2 + kh + a_kof) * 2);
                ldm_x4(fAh, uAh + ao);
                ldm_x4(fAl, uAl + ao);
                #pragma unroll
                for (int nb = 0; nb < 2; ++nb) {
                    mma_bf16(acc[mi][nb * 2 + 0], fAh, bh[nb][0], bh[nb][1]);
                    mma_bf16(acc[mi][nb * 2 + 1], fAh, bh[nb][2], bh[nb][3]);
                    mma_bf16(acc[mi][nb * 2 + 0], fAh, bl[nb][0], bl[nb][1]);
                    mma_bf16(acc[mi][nb * 2 + 1], fAh, bl[nb][2], bl[nb][3]);
                    mma_bf16(acc[mi][nb * 2 + 0], fAl, bh[nb][0], bh[nb][1]);
                    mma_bf16(acc[mi][nb * 2 + 1], fAl, bh[nb][2], bh[nb][3]);
                }
            }
        }
        __syncthreads();
    }

    // Epilogue: c-frag map: rows qr, qr+8; cols qc, qc+1
    const int qr = lane >> 2, qc = (lane & 3) * 2;
    #pragma unroll
    for (int mi = 0; mi < 4; ++mi) {
        int r1 = row0 + mwarp * 64 + mi * 16 + qr;
        int r2 = r1 + 8;
        float m1 = g_validsel[r1] ? 1.0f : 0.0f;
        float m2 = g_validsel[r2] ? 1.0f : 0.0f;
        #pragma unroll
        for (int ni = 0; ni < 4; ++ni) {
            int cg = col0 + nwarp * 32 + ni * 8 + qc;
            float bza = b2[cg], bzb = b2[cg + 1];
            float2 o1, o2;
            o1.x = m1 * (acc[mi][ni][0] + bza);
            o1.y = m1 * (acc[mi][ni][1] + bzb);
            o2.x = m2 * (acc[mi][ni][2] + bza);
            o2.y = m2 * (acc[mi][ni][3] + bzb);
            *(float2*)&out[OUT_Q_OFF + (size_t)r1 * DD + cg] = o1;
            *(float2*)&out[OUT_Q_OFF + (size_t)r2 * DD + cg] = o2;
        }
    }
}

// ============================================================================
extern "C" void kernel_launch(void* const* d_in, const int* in_sizes, int n_in,
                              void* d_out, int out_size) {
    int i_boxes = -1, i_w1 = -1, i_w2 = -1;
    int i512[2] = {-1, -1}; int n512 = 0;
    int iN[3]   = {-1, -1, -1}; int nN = 0;
    for (int i = 0; i < n_in; ++i) {
        int s = in_sizes[i];
        if (s == BB * NN * 9) i_boxes = i;
        else if (s == INF * DD) i_w1 = i;
        else if (s == DD * DD) i_w2 = i;
        else if (s == DD) { if (n512 < 2) i512[n512++] = i; }
        else if (s == BB * NN) { if (nN < 3) iN[nN++] = i; }
    }
    if (i_boxes < 0 || i_w1 < 0 || i_w2 < 0 || n512 < 2 || nN < 3) {
        i_boxes = 0; iN[0] = 1; i_w1 = 2; i512[0] = 3; i_w2 = 4; i512[1] = 5;
        iN[1] = 6; iN[2] = 7;
    }

    const float* boxes = (const float*)d_in[i_boxes];
    const float* w1    = (const float*)d_in[i_w1];
    const float* b1    = (const float*)d_in[i512[0]];
    const float* w2    = (const float*)d_in[i_w2];
    const float* b2    = (const float*)d_in[i512[1]];
    float* out = (float*)d_out;

    cudaFuncSetAttribute(k_gemm1t, cudaFuncAttributeMaxDynamicSharedMemorySize,
                         G1_SMEM);
    cudaFuncSetAttribute(k_gemm2_mma, cudaFuncAttributeMaxDynamicSharedMemorySize,
                         G2_SMEM);

    k_classify<<<1, 256>>>((const unsigned*)d_in[iN[0]],
                           (const unsigned*)d_in[iN[1]],
                           (const unsigned*)d_in[iN[2]]);
    k_canon_keys<<<(BB * NN) / 256, 256>>>();
    k_select_topk<<<BB, 1024>>>();
    k_prep_w1<<<(DD * K1P + 255) / 256, 256>>>(w1);
    k_prep_w2<<<(DD * DD) / 256, 256>>>(w2);
    k_gather<<<MM / 256, 256>>>(boxes, out);
    k_gemm1t<<<dim3(2, MM / 128), 256, G1_SMEM>>>(b1);
    k_gemm2_mma<<<dim3(2, MM / 128), 512, G2_SMEM>>>(b2, out);
}

// round 15
// speedup vs baseline: 1.1089x; 1.1089x over previous
#include <cuda_runtime.h>
#include <cuda_bf16.h>
#include <cstdint>
#include <math.h>

// Problem constants
#define BB 64
#define NN 16384
#define QQ 2048          // Q_LIDAR
#define NC 23            // NUM_CLASSES
#define DD 512           // MODEL_DIM
#define INF 33           // INPUT_DIM
#define K1P 48           // padded stage-1 K (33 -> 48, 3 x k16)
#define MM (BB * QQ)     // 131072 total selected rows

// Output layout: queries [B,Q,512] | refs [B,Q,3] | scores [B,Q]  (all f32)
#define OUT_Q_OFF 0
#define OUT_R_OFF ((size_t)BB * QQ * DD)
#define OUT_S_OFF (OUT_R_OFF + (size_t)BB * QQ * 3)

// ---- device scratch (no allocations allowed) ----
__device__ __align__(16) unsigned long long g_keys[(size_t)BB * NN];   // 8 MB
__device__ int g_idx[BB * QQ];                                         // 512 KB
__device__ __align__(16) __nv_bfloat16 g_feat_hi[(size_t)MM * K1P];    // 12.6 MB
__device__ __align__(16) __nv_bfloat16 g_feat_lo[(size_t)MM * K1P];    // 12.6 MB
__device__ unsigned char g_validsel[MM];                               // 128 KB
__device__ __align__(16) __nv_bfloat16 g_hid_hi[(size_t)MM * DD];      // 134 MB
__device__ __align__(16) __nv_bfloat16 g_hid_lo[(size_t)MM * DD];      // 134 MB
__device__ __align__(16) __nv_bfloat16 g_w1t_hi[(size_t)DD * K1P];     // 48 KB [n][k]
__device__ __align__(16) __nv_bfloat16 g_w1t_lo[(size_t)DD * K1P];
__device__ __align__(16) __nv_bfloat16 g_w2t_hi[(size_t)DD * DD];      // 512 KB [n][k]
__device__ __align__(16) __nv_bfloat16 g_w2t_lo[(size_t)DD * DD];

// Canonicalized inputs (robust to input order / dtype conversion)
__device__ unsigned long long g_ptr_scores, g_ptr_labels, g_ptr_valid;
__device__ int g_lab_mode;   // 0=int32, 1=int64, 2=float32
__device__ int g_val_mode;   // 0=uint8, 1=int32, 2=float32
__device__ __align__(16) float g_scores_c[(size_t)BB * NN];
__device__ __align__(16) int   g_labels_c[(size_t)BB * NN];
__device__ unsigned char g_valid_c[(size_t)BB * NN];

// ============================================================================
// Kernel 0a: classify the three 1048576-element buffers by content.
// ============================================================================
__global__ void k_classify(const unsigned* c0, const unsigned* c1, const unsigned* c2) {
    const unsigned* cands[3] = {c0, c1, c2};
    __shared__ int cls[3], mode[3];
    for (int ci = 0; ci < 3; ++ci) {
        const unsigned* p = cands[ci];
        int bytes01 = 1, words01 = 1, lt23 = 1, oddz = 1, fbool = 1, fint = 1;
        for (int i = threadIdx.x; i < 1024; i += blockDim.x) {
            unsigned w = p[i];
            unsigned b0 = w & 255u, b1 = (w >> 8) & 255u, b2 = (w >> 16) & 255u, b3 = w >> 24;
            if (b0 > 1u || b1 > 1u || b2 > 1u || b3 > 1u) bytes01 = 0;
            if (w > 1u) words01 = 0;
            if (w >= 23u) lt23 = 0;
            if ((i & 1) && w) oddz = 0;
            float f = __uint_as_float(w);
            if (!(f == 0.0f || f == 1.0f)) fbool = 0;
            if (!(f == 0.0f || (f >= 1.0f && f < 23.0f && f == floorf(f)))) fint = 0;
        }
        bytes01 = __syncthreads_and(bytes01);
        words01 = __syncthreads_and(words01);
        lt23    = __syncthreads_and(lt23);
        oddz    = __syncthreads_and(oddz);
        fbool   = __syncthreads_and(fbool);
        fint    = __syncthreads_and(fint);
        if (threadIdx.x == 0) {
            if (bytes01)      { cls[ci] = 2; mode[ci] = words01 ? 1 : 0; }
            else if (lt23)    { cls[ci] = 1; mode[ci] = oddz ? 1 : 0; }
            else if (fbool)   { cls[ci] = 2; mode[ci] = 2; }
            else if (fint)    { cls[ci] = 1; mode[ci] = 2; }
            else              { cls[ci] = 0; mode[ci] = 0; }
        }
        __syncthreads();
    }
    if (threadIdx.x == 0) {
        bool ok = (cls[0] + cls[1] + cls[2] == 3) &&
                  cls[0] != cls[1] && cls[0] != cls[2] && cls[1] != cls[2];
        if (!ok) { cls[0] = 0; cls[1] = 1; cls[2] = 2; mode[1] = 1; mode[2] = 0; }
        for (int ci = 0; ci < 3; ++ci) {
            unsigned long long pv = (unsigned long long)cands[ci];
            if (cls[ci] == 0)      g_ptr_scores = pv;
            else if (cls[ci] == 1) { g_ptr_labels = pv; g_lab_mode = mode[ci]; }
            else                   { g_ptr_valid = pv;  g_val_mode = mode[ci]; }
        }
    }
}

// ============================================================================
// Kernel 0b: canonicalize + build sort keys (fused).
// ============================================================================
__global__ void k_canon_keys() {
    int t = blockIdx.x * blockDim.x + threadIdx.x;
    if (t >= BB * NN) return;
    const unsigned* sp = (const unsigned*)g_ptr_scores;
    float sc = __uint_as_float(sp[t]);
    g_scores_c[t] = sc;

    const unsigned* lp = (const unsigned*)g_ptr_labels;
    int lm = g_lab_mode;
    int lab = (lm == 1) ? (int)lp[2 * t]
            : (lm == 2) ? (int)__uint_as_float(lp[t])
                        : (int)lp[t];
    g_labels_c[t] = lab;

    int vm = g_val_mode;
    unsigned char v;
    if (vm == 0)      v = (((const unsigned char*)g_ptr_valid)[t] != 0);
    else if (vm == 1) v = (((const unsigned*)g_ptr_valid)[t] != 0u);
    else              v = (__uint_as_float(((const unsigned*)g_ptr_valid)[t]) != 0.0f);
    g_valid_c[t] = v;

    float s = v ? sc : -1e30f;
    unsigned u = __float_as_uint(s);
    u = (u & 0x80000000u) ? ~u : (u | 0x80000000u);
    unsigned i = (unsigned)(t & (NN - 1));
    g_keys[t] = ((unsigned long long)u << 32) | (unsigned)(~i);
}

// ============================================================================
// Kernel 2: per-batch exact top-K (ordered). One CTA per batch. 1024 threads.
// ============================================================================
__global__ void k_select_topk() {
    __shared__ unsigned long long skey[QQ];
    __shared__ unsigned int hist[256];
    __shared__ int s_digit, s_k;
    __shared__ unsigned int s_cnt;

    const int b = blockIdx.x;
    const int tid = threadIdx.x;
    const int bd = blockDim.x;
    const unsigned long long* keys = g_keys + (size_t)b * NN;
    const ulonglong2* keys2 = (const ulonglong2*)keys;

    unsigned long long prefix = 0;
    int k = QQ;

    #pragma unroll 1
    for (int pass = 0; pass < 8; ++pass) {
        const int shift = 56 - pass * 8;
        const unsigned long long mask = pass ? (~0ULL << (64 - 8 * pass)) : 0ULL;
        for (int i = tid; i < 256; i += bd) hist[i] = 0;
        __syncthreads();
        for (int i = tid; i < NN / 2; i += bd) {
            ulonglong2 kv = keys2[i];
            if ((kv.x & mask) == prefix)
                atomicAdd(&hist[(unsigned)(kv.x >> shift) & 0xFFu], 1u);
            if ((kv.y & mask) == prefix)
                atomicAdd(&hist[(unsigned)(kv.y >> shift) & 0xFFu], 1u);
        }
        __syncthreads();
        if (tid == 0) {
            int run = 0, d = 255;
            for (; d >= 0; --d) {
                int h = (int)hist[d];
                if (run + h >= k) break;
                run += h;
            }
            s_digit = d;
            s_k = k - run;
        }
        __syncthreads();
        prefix |= ((unsigned long long)(unsigned)s_digit) << shift;
        k = s_k;
        __syncthreads();
    }
    const unsigned long long thr = prefix;

    if (tid == 0) s_cnt = 0;
    for (int i = tid; i < QQ; i += bd) skey[i] = 0;
    __syncthreads();
    for (int i = tid; i < NN / 2; i += bd) {
        ulonglong2 kv = keys2[i];
        if (kv.x >= thr) {
            unsigned p = atomicAdd(&s_cnt, 1u);
            if (p < QQ) skey[p] = kv.x;
        }
        if (kv.y >= thr) {
            unsigned p = atomicAdd(&s_cnt, 1u);
            if (p < QQ) skey[p] = kv.y;
        }
    }
    __syncthreads();

    for (int kk = 2; kk <= QQ; kk <<= 1) {
        for (int j = kk >> 1; j > 0; j >>= 1) {
            for (int t = tid; t < QQ; t += bd) {
                int ixj = t ^ j;
                if (ixj > t) {
                    unsigned long long a = skey[t], c = skey[ixj];
                    bool desc = ((t & kk) == 0);
                    if (desc ? (a < c) : (a > c)) { skey[t] = c; skey[ixj] = a; }
                }
            }
            __syncthreads();
        }
    }

    for (int t = tid; t < QQ; t += bd)
        g_idx[b * QQ + t] = (int)(~(unsigned)(skey[t] & 0xFFFFFFFFULL));
}

// ============================================================================
// Kernel 3: gather + SPLIT features to bf16 hi/lo (padded to 48 cols),
// plus refs/scores outputs. Split here is bit-identical to the old
// in-GEMM1 split, so downstream math is unchanged.
// ============================================================================
__global__ void k_gather(const float* __restrict__ boxes,
                         float* __restrict__ out) {
    int r = blockIdx.x * blockDim.x + threadIdx.x;
    if (r >= MM) return;
    int b = r >> 11;
    int i = g_idx[r];
    size_t src = (size_t)b * NN + i;

    const float* bx = boxes + src * 9;
    float sc = g_scores_c[src];
    int lab = g_labels_c[src];
    unsigned char v = g_valid_c[src];

    float f0 = bx[0], f1 = bx[1], f2 = bx[2];

    __align__(16) __nv_bfloat16 fh[K1P], fl[K1P];
    #pragma unroll
    for (int j = 0; j < K1P; ++j) { fh[j] = __float2bfloat16(0.0f); fl[j] = __float2bfloat16(0.0f); }

    #pragma unroll
    for (int j = 0; j < 9; ++j) {
        float fv = bx[j];
        __nv_bfloat16 hi = __float2bfloat16(fv);
        fh[j] = hi;
        fl[j] = __float2bfloat16(fv - __bfloat162float(hi));
    }
    {
        __nv_bfloat16 hi = __float2bfloat16(sc);
        fh[9] = hi;
        fl[9] = __float2bfloat16(sc - __bfloat162float(hi));
    }
    if (lab >= 0 && lab < NC) fh[10 + lab] = __float2bfloat16(1.0f);  // exact; lo = 0

    float4* dh = (float4*)(g_feat_hi + (size_t)r * K1P);
    float4* dl = (float4*)(g_feat_lo + (size_t)r * K1P);
    const float4* sh = (const float4*)fh;
    const float4* sl = (const float4*)fl;
    #pragma unroll
    for (int j = 0; j < 6; ++j) { dh[j] = sh[j]; dl[j] = sl[j]; }

    g_validsel[r] = v;

    float* refo = out + OUT_R_OFF + (size_t)r * 3;
    refo[0] = v ? f0 : 0.0f;
    refo[1] = v ? f1 : 0.0f;
    refo[2] = v ? f2 : 0.0f;
    out[OUT_S_OFF + r] = v ? sc : 0.0f;
}

// ============================================================================
// Kernel 3b: weight prep. w1 -> w1t[n][48] split; w2 -> w2t[n][k] split.
// ============================================================================
__global__ void k_prep_w1(const float* __restrict__ w1) {
    int idx = blockIdx.x * blockDim.x + threadIdx.x;
    if (idx >= DD * K1P) return;
    int n = idx / K1P, k = idx - n * K1P;
    float v = (k < INF) ? w1[(size_t)k * DD + n] : 0.0f;
    __nv_bfloat16 hi = __float2bfloat16(v);
    g_w1t_hi[idx] = hi;
    g_w1t_lo[idx] = __float2bfloat16(v - __bfloat162float(hi));
}
__global__ void k_prep_w2(const float* __restrict__ w2) {
    int idx = blockIdx.x * blockDim.x + threadIdx.x;
    if (idx >= DD * DD) return;
    int n = idx >> 9, k = idx & (DD - 1);
    float v = w2[(size_t)k * DD + n];
    __nv_bfloat16 hi = __float2bfloat16(v);
    g_w2t_hi[idx] = hi;
    g_w2t_lo[idx] = __float2bfloat16(v - __bfloat162float(hi));
}

// ============================================================================
// mma helpers
// ============================================================================
__device__ __forceinline__ uint32_t smem_u32(const void* p) {
    uint32_t a;
    asm("{ .reg .u64 t; cvta.to.shared.u64 t, %1; cvt.u32.u64 %0, t; }" : "=r"(a) : "l"(p));
    return a;
}
__device__ __forceinline__ void ldm_x4(uint32_t* r, uint32_t addr) {
    asm volatile("ldmatrix.sync.aligned.m8n8.x4.shared.b16 {%0,%1,%2,%3}, [%4];"
        : "=r"(r[0]), "=r"(r[1]), "=r"(r[2]), "=r"(r[3]) : "r"(addr));
}
__device__ __forceinline__ void mma_bf16(float* c, const uint32_t* a, uint32_t b0, uint32_t b1) {
    asm volatile("mma.sync.aligned.m16n8k16.row.col.f32.bf16.bf16.f32 "
        "{%0,%1,%2,%3}, {%4,%5,%6,%7}, {%8,%9}, {%0,%1,%2,%3};"
        : "+f"(c[0]), "+f"(c[1]), "+f"(c[2]), "+f"(c[3])
        : "r"(a[0]), "r"(a[1]), "r"(a[2]), "r"(a[3]), "r"(b0), "r"(b1));
}
__device__ __forceinline__ void cp16(uint32_t dst, const void* src) {
    asm volatile("cp.async.cg.shared.global [%0], [%1], 16;" :: "r"(dst), "l"(src));
}
__device__ __forceinline__ void split_pack(float a, float b, uint32_t& hip, uint32_t& lop) {
    __nv_bfloat16 ha = __float2bfloat16(a), hb = __float2bfloat16(b);
    __nv_bfloat16 la = __float2bfloat16(a - __bfloat162float(ha));
    __nv_bfloat16 lb = __float2bfloat16(b - __bfloat162float(hb));
    hip = (uint32_t)__bfloat16_as_ushort(ha) | ((uint32_t)__bfloat16_as_ushort(hb) << 16);
    lop = (uint32_t)__bfloat16_as_ushort(la) | ((uint32_t)__bfloat16_as_ushort(lb) << 16);
}

// ============================================================================
// Kernel 4: GEMM1 tensorized. hidden = relu(feat @ w1 + b1).
// Feat now pre-split bf16 hi/lo in GMEM -> pure cp.async load phase.
// CTA 128x256, 8 warps (2m x 4n), warp tile 64x64. grid (2, M/128).
// ============================================================================
#define G1_FP 56
#define G1_WP 56
#define G1_OFF_FH 0
#define G1_OFF_FL 14336
#define G1_OFF_WH 28672
#define G1_OFF_WL 57344
#define G1_SMEM   86016

__global__ void __launch_bounds__(256, 1) k_gemm1t(const float* __restrict__ b1) {
    extern __shared__ __align__(16) char smem[];
    const uint32_t sb = smem_u32(smem);
    const int tid = threadIdx.x;
    const int wid = tid >> 5, lane = tid & 31;
    const int mwarp = wid & 1;
    const int nwarp = wid >> 1;
    const int row0 = blockIdx.y * 128;
    const int col0 = blockIdx.x * 256;

    const int qr = lane >> 2, qc = (lane & 3) * 2;
    const int a_r = lane & 15;
    const int a_k = (lane >> 4) * 8;
    const int b_r = (lane & 7) + (lane >> 4) * 8;
    const int b_k = ((lane >> 3) & 1) * 8;

    // w1t slice: 256 n-rows x 48 halves, 6 cp16/row
    #pragma unroll
    for (int it = 0; it < 6; ++it) {
        int idx = tid + it * 256;
        int n = idx / 6, p = idx - n * 6;
        uint32_t d = sb + G1_OFF_WH + n * (G1_WP * 2) + p * 16;
        size_t so = ((size_t)(col0 + n) * K1P + p * 8);
        cp16(d, g_w1t_hi + so);
        cp16(d + (G1_OFF_WL - G1_OFF_WH), g_w1t_lo + so);
    }
    // feat: 128 rows x 48 halves, 6 cp16/row (pre-split, pre-padded)
    #pragma unroll
    for (int it = 0; it < 3; ++it) {
        int idx = tid + it * 256;
        int r = idx / 6, p = idx - r * 6;
        uint32_t d = sb + G1_OFF_FH + r * (G1_FP * 2) + p * 16;
        size_t so = ((size_t)(row0 + r) * K1P + p * 8);
        cp16(d, g_feat_hi + so);
        cp16(d + (G1_OFF_FL - G1_OFF_FH), g_feat_lo + so);
    }
    asm volatile("cp.async.commit_group;" ::: "memory");
    asm volatile("cp.async.wait_group 0;" ::: "memory");
    __syncthreads();

    float acc[4][8][4];
    #pragma unroll
    for (int mi = 0; mi < 4; ++mi)
        #pragma unroll
        for (int ni = 0; ni < 8; ++ni)
            #pragma unroll
            for (int q = 0; q < 4; ++q) acc[mi][ni][q] = 0.0f;

    const uint32_t uFh = sb + G1_OFF_FH, uFl = sb + G1_OFF_FL;
    const uint32_t uWh = sb + G1_OFF_WH, uWl = sb + G1_OFF_WL;
    #pragma unroll
    for (int kk = 0; kk < 3; ++kk) {
        const int kh = kk * 16;
        uint32_t fAh[4][4], fAl[4][4];
        #pragma unroll
        for (int mi = 0; mi < 4; ++mi) {
            uint32_t ao = (uint32_t)(((mwarp * 64 + mi * 16 + a_r) * G1_FP + kh + a_k) * 2);
            ldm_x4(fAh[mi], uFh + ao);
            ldm_x4(fAl[mi], uFl + ao);
        }
        #pragma unroll
        for (int nb = 0; nb < 4; ++nb) {
            uint32_t bh[4], bl[4];
            uint32_t bo = (uint32_t)(((nwarp * 64 + nb * 16 + b_r) * G1_WP + kh + b_k) * 2);
            ldm_x4(bh, uWh + bo);
            ldm_x4(bl, uWl + bo);
            #pragma unroll
            for (int mi = 0; mi < 4; ++mi) {
                mma_bf16(acc[mi][nb * 2 + 0], fAh[mi], bh[0], bh[1]);
                mma_bf16(acc[mi][nb * 2 + 1], fAh[mi], bh[2], bh[3]);
                mma_bf16(acc[mi][nb * 2 + 0], fAh[mi], bl[0], bl[1]);
                mma_bf16(acc[mi][nb * 2 + 1], fAh[mi], bl[2], bl[3]);
                mma_bf16(acc[mi][nb * 2 + 0], fAl[mi], bh[0], bh[1]);
                mma_bf16(acc[mi][nb * 2 + 1], fAl[mi], bh[2], bh[3]);
            }
        }
    }

    #pragma unroll
    for (int mi = 0; mi < 4; ++mi) {
        int r1 = row0 + mwarp * 64 + mi * 16 + qr;
        int r2 = r1 + 8;
        #pragma unroll
        for (int ni = 0; ni < 8; ++ni) {
            int cg = col0 + nwarp * 64 + ni * 8 + qc;
            float ba = b1[cg], bb = b1[cg + 1];
            float h1a = fmaxf(acc[mi][ni][0] + ba, 0.0f);
            float h1b = fmaxf(acc[mi][ni][1] + bb, 0.0f);
            float h2a = fmaxf(acc[mi][ni][2] + ba, 0.0f);
            float h2b = fmaxf(acc[mi][ni][3] + bb, 0.0f);
            uint32_t hp, lp;
            split_pack(h1a, h1b, hp, lp);
            *(uint32_t*)&g_hid_hi[(size_t)r1 * DD + cg] = hp;
            *(uint32_t*)&g_hid_lo[(size_t)r1 * DD + cg] = lp;
            split_pack(h2a, h2b, hp, lp);
            *(uint32_t*)&g_hid_hi[(size_t)r2 * DD + cg] = hp;
            *(uint32_t*)&g_hid_lo[(size_t)r2 * DD + cg] = lp;
        }
    }
}

// ============================================================================
// Kernel 5: GEMM2 (R13/R9-identical best config). mma.sync bf16, 3-term
// split, cp.async 2-stage pipeline. CTA 128x256, 8 warps (2m x 4n),
// warp tile 64x64, BK=64 (8 chunks), pitch 72 halves.
// ============================================================================
#define ALD2 72
#define A_SZ 18432        // 128*72*2
#define B_SZ 36864        // 256*72*2
#define OFF_AH 0
#define OFF_AL A_SZ
#define OFF_BH (2 * A_SZ)
#define OFF_BL (2 * A_SZ + B_SZ)
#define STAGE_SZ (2 * A_SZ + 2 * B_SZ)   // 110592
#define G2_SMEM (2 * STAGE_SZ)           // 221184

__global__ void __launch_bounds__(256, 1) k_gemm2_mma(const float* __restrict__ b2,
                                                      float* __restrict__ out) {
    extern __shared__ __align__(16) char smem[];
    const uint32_t sb = smem_u32(smem);

    const int tid = threadIdx.x;
    const int wid = tid >> 5, lane = tid & 31;
    const int mwarp = wid & 1;        // 2 m-groups of 64 rows
    const int nwarp = wid >> 1;       // 4 n-groups of 64 cols
    const int row0 = blockIdx.y * 128;
    const int col0 = blockIdx.x * 256;

    const __nv_bfloat16* Ah = g_hid_hi + (size_t)row0 * DD;
    const __nv_bfloat16* Al = g_hid_lo + (size_t)row0 * DD;
    const __nv_bfloat16* Bh = g_w2t_hi + (size_t)col0 * DD;
    const __nv_bfloat16* Bl = g_w2t_lo + (size_t)col0 * DD;

    const int a_row = mwarp * 64 + (lane & 15);                    // + mi*16
    const int a_kof = (lane >> 4) * 8;
    const int b_row = nwarp * 64 + (lane & 7) + (lane >> 4) * 8;   // + nb*16
    const int b_kof = ((lane >> 3) & 1) * 8;

    float acc[4][8][4];
    #pragma unroll
    for (int mi = 0; mi < 4; ++mi)
        #pragma unroll
        for (int ni = 0; ni < 8; ++ni)
            #pragma unroll
            for (int q = 0; q < 4; ++q) acc[mi][ni][q] = 0.0f;

    auto load_chunk = [&](int c, int stage) {
        const int kc = c * 64;
        const uint32_t sbase = sb + stage * STAGE_SZ;
        #pragma unroll
        for (int it = 0; it < 4; ++it) {             // A: 128 rows x 64 halves
            int idx = tid + it * 256;                // 1024 pieces of 16 B
            int r = idx >> 3, p = idx & 7;
            size_t src = (size_t)r * DD + kc + p * 8;
            uint32_t d = sbase + OFF_AH + r * (ALD2 * 2) + p * 16;
            cp16(d, Ah + src);
            cp16(d + A_SZ, Al + src);
        }
        #pragma unroll
        for (int it = 0; it < 8; ++it) {             // B: 256 rows x 64 halves
            int idx = tid + it * 256;                // 2048 pieces
            int n = idx >> 3, p = idx & 7;
            size_t src = (size_t)n * DD + kc + p * 8;
            uint32_t d = sbase + OFF_BH + n * (ALD2 * 2) + p * 16;
            cp16(d, Bh + src);
            cp16(d + B_SZ, Bl + src);
        }
        asm volatile("cp.async.commit_group;" ::: "memory");
    };

    load_chunk(0, 0);

    #pragma unroll 1
    for (int c = 0; c < 8; ++c) {
        if (c + 1 < 8) {
            load_chunk(c + 1, (c + 1) & 1);
            asm volatile("cp.async.wait_group 1;" ::: "memory");
        } else {
            asm volatile("cp.async.wait_group 0;" ::: "memory");
        }
        __syncthreads();

        const uint32_t sbase = sb + (c & 1) * STAGE_SZ;
        const uint32_t uAh = sbase + OFF_AH, uAl = sbase + OFF_AL;
        const uint32_t uBh = sbase + OFF_BH, uBl = sbase + OFF_BL;

        #pragma unroll
        for (int kk = 0; kk < 4; ++kk) {
            const int kh = kk * 16;
            uint32_t fAh[4][4], fAl[4][4];
            #pragma unroll
            for (int mi = 0; mi < 4; ++mi) {
                uint32_t ao = (uint32_t)(((a_row + mi * 16) * ALD2 + kh + a_kof) * 2);
                ldm_x4(fAh[mi], uAh + ao);
                ldm_x4(fAl[mi], uAl + ao);
            }
            #pragma unroll
            for (int nb = 0; nb < 4; ++nb) {
                uint32_t bh[4], bl[4];
                uint32_t bo = (uint32_t)(((b_row + nb * 16) * ALD2 + kh + b_kof) * 2);
                ldm_x4(bh, uBh + bo);
                ldm_x4(bl, uBl + bo);
                #pragma unroll
                for (int mi = 0; mi < 4; ++mi) {
                    mma_bf16(acc[mi][nb * 2 + 0], fAh[mi], bh[0], bh[1]);
                    mma_bf16(acc[mi][nb * 2 + 1], fAh[mi], bh[2], bh[3]);
                    mma_bf16(acc[mi][nb * 2 + 0], fAh[mi], bl[0], bl[1]);
                    mma_bf16(acc[mi][nb * 2 + 1], fAh[mi], bl[2], bl[3]);
                    mma_bf16(acc[mi][nb * 2 + 0], fAl[mi], bh[0], bh[1]);
                    mma_bf16(acc[mi][nb * 2 + 1], fAl[mi], bh[2], bh[3]);
                }
            }
        }
        __syncthreads();
    }

    // Epilogue: c-frag map: rows qr, qr+8; cols qc, qc+1
    const int qr = lane >> 2, qc = (lane & 3) * 2;
    #pragma unroll
    for (int mi = 0; mi < 4; ++mi) {
        int r1 = row0 + mwarp * 64 + mi * 16 + qr;
        int r2 = r1 + 8;
        float m1 = g_validsel[r1] ? 1.0f : 0.0f;
        float m2 = g_validsel[r2] ? 1.0f : 0.0f;
        #pragma unroll
        for (int ni = 0; ni < 8; ++ni) {
            int cg = col0 + nwarp * 64 + ni * 8 + qc;
            float bza = b2[cg], bzb = b2[cg + 1];
            float2 o1, o2;
            o1.x = m1 * (acc[mi][ni][0] + bza);
            o1.y = m1 * (acc[mi][ni][1] + bzb);
            o2.x = m2 * (acc[mi][ni][2] + bza);
            o2.y = m2 * (acc[mi][ni][3] + bzb);
            *(float2*)&out[OUT_Q_OFF + (size_t)r1 * DD + cg] = o1;
            *(float2*)&out[OUT_Q_OFF + (size_t)r2 * DD + cg] = o2;
        }
    }
}

// ============================================================================
extern "C" void kernel_launch(void* const* d_in, const int* in_sizes, int n_in,
                              void* d_out, int out_size) {
    int i_boxes = -1, i_w1 = -1, i_w2 = -1;
    int i512[2] = {-1, -1}; int n512 = 0;
    int iN[3]   = {-1, -1, -1}; int nN = 0;
    for (int i = 0; i < n_in; ++i) {
        int s = in_sizes[i];
        if (s == BB * NN * 9) i_boxes = i;
        else if (s == INF * DD) i_w1 = i;
        else if (s == DD * DD) i_w2 = i;
        else if (s == DD) { if (n512 < 2) i512[n512++] = i; }
        else if (s == BB * NN) { if (nN < 3) iN[nN++] = i; }
    }
    if (i_boxes < 0 || i_w1 < 0 || i_w2 < 0 || n512 < 2 || nN < 3) {
        i_boxes = 0; iN[0] = 1; i_w1 = 2; i512[0] = 3; i_w2 = 4; i512[1] = 5;
        iN[1] = 6; iN[2] = 7;
    }

    const float* boxes = (const float*)d_in[i_boxes];
    const float* w1    = (const float*)d_in[i_w1];
    const float* b1    = (const float*)d_in[i512[0]];
    const float* w2    = (const float*)d_in[i_w2];
    const float* b2    = (const float*)d_in[i512[1]];
    float* out = (float*)d_out;

    cudaFuncSetAttribute(k_gemm1t, cudaFuncAttributeMaxDynamicSharedMemorySize,
                         G1_SMEM);
    cudaFuncSetAttribute(k_gemm2_mma, cudaFuncAttributeMaxDynamicSharedMemorySize,
                         G2_SMEM);

    k_classify<<<1, 256>>>((const unsigned*)d_in[iN[0]],
                           (const unsigned*)d_in[iN[1]],
                           (const unsigned*)d_in[iN[2]]);
    k_canon_keys<<<(BB * NN) / 256, 256>>>();
    k_select_topk<<<BB, 1024>>>();
    k_prep_w1<<<(DD * K1P + 255) / 256, 256>>>(w1);
    k_prep_w2<<<(DD * DD) / 256, 256>>>(w2);
    k_gather<<<MM / 256, 256>>>(boxes, out);
    k_gemm1t<<<dim3(2, MM / 128), 256, G1_SMEM>>>(b1);
    k_gemm2_mma<<<dim3(2, MM / 128), 256, G2_SMEM>>>(b2, out);
}